// round 8
// baseline (speedup 1.0000x reference)
#include <cuda_runtime.h>
#include <cstdint>

#define BB      32
#define HH      32
#define KVHH    8
#define DD      128
#define SS      2048
#define REP     4          // HH/KVHH
#define SPLITS  8
#define CHUNK   (SS/SPLITS)        // 256
#define TPB     256
#define NWARPS  8
#define TPW     (CHUNK/NWARPS)     // 32 tokens per warp
#define NB      (TPW/4)            // 8 batches of 4
#define SCALE_F 0.08838834764831845f   // 1/sqrt(128)
#define ESHIFT  8.0f                   // uniform exp-arg shift; cancels in num/den

// ---------------- device scratch (no allocs allowed) ----------------
// tab4[pos][lane] = {cos(2l), cos(2l+1), sin(2l), sin(2l+1)}  (1 MB)
__device__ float4 g_tab4[SS * 32];
__device__ float g_pacc[BB * KVHH * SPLITS * REP * DD]; // 4 MB split partials (unnormalized)
__device__ float g_pl[BB * KVHH * SPLITS * REP];

// ---------------- rope table (fast MUFU trig with fp32 range reduction) ----------------
__global__ void rope_table_kernel() {
    int idx = blockIdx.x * blockDim.x + threadIdx.x;    // SS*32
    if (idx >= SS * 32) return;
    int pos = idx >> 5, l = idx & 31;
    float inv0 = exp2f(-(float)(2 * l)     * (13.287712379549449f / 64.0f));
    float inv1 = exp2f(-(float)(2 * l + 1) * (13.287712379549449f / 64.0f));
    float a0 = (float)pos * inv0, a1 = (float)pos * inv1;
    float k0 = rintf(a0 * 0.15915494309189535f);
    float k1 = rintf(a1 * 0.15915494309189535f);
    float r0 = fmaf(k0, -6.283185307179586f, a0);
    float r1 = fmaf(k1, -6.283185307179586f, a1);
    float c0, s0, c1, s1;
    __sincosf(r0, &s0, &c0);
    __sincosf(r1, &s1, &c1);
    g_tab4[idx] = make_float4(c0, c1, s0, s1);
}

// ---------------- main split attention kernel (single pass, no max) ----------------
__global__ void __launch_bounds__(TPB, 3)
paged_attn_main(const float* __restrict__ query,
                const float* __restrict__ k_cache,
                const float* __restrict__ v_cache,
                const int*   __restrict__ slot_mapping,
                const int*   __restrict__ positions)
{
    const int cta   = blockIdx.x;
    const int split = cta & (SPLITS - 1);
    const int kvh   = (cta >> 3) & (KVHH - 1);
    const int b     = cta >> 6;
    const int tid   = threadIdx.x;
    const int w     = tid >> 5;
    const int lane  = tid & 31;

    __shared__ __align__(16) float s_acc[REP][NWARPS][DD];   // 16 KB
    __shared__ float s_l[NWARPS][REP];

    const int sbase = split * CHUNK + w * TPW;
    const int* smap = slot_mapping + b * SS + sbase;
    const int* pmap = positions + b * SS + sbase;

    // ---- batch-0 slot/pos loads issued first (overlap with Q prologue) ----
    int sl0, sl1, sl2, sl3, ps0, ps1, ps2, ps3;
    sl0 = __ldg(smap + 0); sl1 = __ldg(smap + 1);
    sl2 = __ldg(smap + 2); sl3 = __ldg(smap + 3);
    ps0 = __ldg(pmap + 0); ps1 = __ldg(pmap + 1);
    ps2 = __ldg(pmap + 2); ps3 = __ldg(pmap + 3);

    // ---- roped + pre-scaled Q; lane owns dims {2l, 2l+1, 2l+64, 2l+65} ----
    const int posQ = positions[b * SS + (SS - 1)];
    const float4 tq = g_tab4[posQ * 32 + lane];
    float4 qr[REP];
#pragma unroll
    for (int r = 0; r < REP; r++) {
        int h = kvh * REP + r;
        const float* qp = query + ((size_t)b * HH + h) * DD;
        float2 qlo = *(const float2*)(qp + 2 * lane);
        float2 qhi = *(const float2*)(qp + 64 + 2 * lane);
        float4 v;
        v.x = fmaf(-qhi.x, tq.z, qlo.x * tq.x) * SCALE_F;
        v.y = fmaf(-qhi.y, tq.w, qlo.y * tq.y) * SCALE_F;
        v.z = fmaf( qlo.x, tq.z, qhi.x * tq.x) * SCALE_F;
        v.w = fmaf( qlo.y, tq.w, qhi.y * tq.y) * SCALE_F;
        qr[r] = v;
    }

    const float* kbase = k_cache + kvh * DD + 2 * lane;
    const float* vbase = v_cache + kvh * DD + 4 * lane;

    float lown = 0.f;   // per-lane-group l (group g == head g)
    float4 acc0 = make_float4(0.f,0.f,0.f,0.f), acc1 = acc0, acc2 = acc0, acc3 = acc0;

#pragma unroll 1
    for (int b2 = 0; b2 < NB; b2++) {
        int sl[4] = {sl0, sl1, sl2, sl3};
        int ps[4] = {ps0, ps1, ps2, ps3};
        // K/V loads (streaming, evict-first) + tab loads — addresses ready
        float2 klo[4], khi[4];
        float4 vv[4], tb[4];
#pragma unroll
        for (int u = 0; u < 4; u++) {
            klo[u] = make_float2(0.f, 0.f);
            khi[u] = make_float2(0.f, 0.f);
            vv[u]  = make_float4(0.f, 0.f, 0.f, 0.f);
            if (sl[u] >= 0) {
                const float* kp = kbase + (size_t)sl[u] * (KVHH * DD);
                klo[u] = __ldcs((const float2*)kp);
                khi[u] = __ldcs((const float2*)(kp + 64));
                vv[u]  = __ldcs((const float4*)(vbase + (size_t)sl[u] * (KVHH * DD)));
            }
            tb[u] = g_tab4[ps[u] * 32 + lane];
        }
        // prefetch next batch's slot/pos while this batch's K/V are in flight
        if (b2 + 1 < NB) {
            const int nb = (b2 + 1) * 4;
            sl0 = __ldg(smap + nb + 0); sl1 = __ldg(smap + nb + 1);
            sl2 = __ldg(smap + nb + 2); sl3 = __ldg(smap + nb + 3);
            ps0 = __ldg(pmap + nb + 0); ps1 = __ldg(pmap + nb + 1);
            ps2 = __ldg(pmap + nb + 2); ps3 = __ldg(pmap + nb + 3);
        }
#pragma unroll
        for (int u = 0; u < 4; u++) {
            // rope K in-lane
            float kr0 = fmaf(-khi[u].x, tb[u].z, klo[u].x * tb[u].x);
            float kr1 = fmaf(-khi[u].y, tb[u].w, klo[u].y * tb[u].y);
            float kr2 = fmaf( klo[u].x, tb[u].z, khi[u].x * tb[u].x);
            float kr3 = fmaf( klo[u].y, tb[u].w, khi[u].y * tb[u].y);
            // per-head partial dots
            float v0 = fmaf(kr3, qr[0].w, fmaf(kr2, qr[0].z, fmaf(kr1, qr[0].y, kr0 * qr[0].x)));
            float v1 = fmaf(kr3, qr[1].w, fmaf(kr2, qr[1].z, fmaf(kr1, qr[1].y, kr0 * qr[1].x)));
            float v2 = fmaf(kr3, qr[2].w, fmaf(kr2, qr[2].z, fmaf(kr1, qr[2].y, kr0 * qr[2].x)));
            float v3 = fmaf(kr3, qr[3].w, fmaf(kr2, qr[3].z, fmaf(kr1, qr[3].y, kr0 * qr[3].x)));
            // width-folding reduce: 9 shuffles; 8-lane group g ends with head g's full score
            float r0 = __shfl_xor_sync(0xffffffffu, v0, 16);
            float r1 = __shfl_xor_sync(0xffffffffu, v1, 16);
            float r2 = __shfl_xor_sync(0xffffffffu, v2, 16);
            float r3 = __shfl_xor_sync(0xffffffffu, v3, 16);
            float t0a = v0 + r0, t1a = v1 + r1, t2a = v2 + r2, t3a = v3 + r3;
            float a0 = (lane & 16) ? t2a : t0a;
            float a1 = (lane & 16) ? t3a : t1a;
            float u0 = a0 + __shfl_xor_sync(0xffffffffu, a0, 8);
            float u1 = a1 + __shfl_xor_sync(0xffffffffu, a1, 8);
            float bsum = (lane & 8) ? u1 : u0;
            bsum += __shfl_xor_sync(0xffffffffu, bsum, 4);
            bsum += __shfl_xor_sync(0xffffffffu, bsum, 2);
            bsum += __shfl_xor_sync(0xffffffffu, bsum, 1);
            // one exp per token (per owning group), then broadcast the 4 head p's
            float p = __expf(bsum - ESHIFT);
            lown += p;
            int src = lane & 7;
            float p0 = __shfl_sync(0xffffffffu, p, src);
            float p1 = __shfl_sync(0xffffffffu, p, src | 8);
            float p2 = __shfl_sync(0xffffffffu, p, src | 16);
            float p3 = __shfl_sync(0xffffffffu, p, src | 24);
            float4 v4 = vv[u];
            acc0.x = fmaf(p0, v4.x, acc0.x); acc0.y = fmaf(p0, v4.y, acc0.y);
            acc0.z = fmaf(p0, v4.z, acc0.z); acc0.w = fmaf(p0, v4.w, acc0.w);
            acc1.x = fmaf(p1, v4.x, acc1.x); acc1.y = fmaf(p1, v4.y, acc1.y);
            acc1.z = fmaf(p1, v4.z, acc1.z); acc1.w = fmaf(p1, v4.w, acc1.w);
            acc2.x = fmaf(p2, v4.x, acc2.x); acc2.y = fmaf(p2, v4.y, acc2.y);
            acc2.z = fmaf(p2, v4.z, acc2.z); acc2.w = fmaf(p2, v4.w, acc2.w);
            acc3.x = fmaf(p3, v4.x, acc3.x); acc3.y = fmaf(p3, v4.y, acc3.y);
            acc3.z = fmaf(p3, v4.z, acc3.z); acc3.w = fmaf(p3, v4.w, acc3.w);
        }
    }

    // ---- per-warp state to smem ----
    if ((lane & 7) == 0) s_l[w][lane >> 3] = lown;
    *(float4*)&s_acc[0][w][lane * 4] = acc0;
    *(float4*)&s_acc[1][w][lane * 4] = acc1;
    *(float4*)&s_acc[2][w][lane * 4] = acc2;
    *(float4*)&s_acc[3][w][lane * 4] = acc3;
    __syncthreads();

    // ---- cross-warp merge (plain sums; no factors needed) ----
    const size_t pidx = (size_t)((b * KVHH + kvh) * SPLITS + split);
    const size_t obase = pidx * (REP * DD);
    for (int idx = tid; idx < REP * DD; idx += TPB) {
        int h = idx >> 7, d = idx & (DD - 1);
        float v = 0.f;
#pragma unroll
        for (int ww = 0; ww < NWARPS; ww++) v += s_acc[h][ww][d];
        g_pacc[obase + idx] = v;
    }
    if (tid < REP) {
        float ls = 0.f;
#pragma unroll
        for (int ww = 0; ww < NWARPS; ww++) ls += s_l[ww][tid];
        g_pl[pidx * REP + tid] = ls;
    }
}

// ---------------- split combine ----------------
__global__ void combine_kernel(float* __restrict__ out) {
    int idx = blockIdx.x * blockDim.x + threadIdx.x;
    if (idx >= BB * HH * DD) return;
    int d = idx & (DD - 1);
    int h = (idx >> 7) & (HH - 1);
    int b = idx >> 12;
    int kvh = h >> 2, r = h & 3;
    int pbase = (b * KVHH + kvh) * SPLITS;

    float num = 0.f, den = 0.f;
#pragma unroll
    for (int s = 0; s < SPLITS; s++) {
        den += g_pl[(pbase + s) * REP + r];
        num += g_pacc[(size_t)(pbase + s) * REP * DD + r * DD + d];
    }
    out[idx] = num / den;
}

// ---------------- launch ----------------
extern "C" void kernel_launch(void* const* d_in, const int* in_sizes, int n_in,
                              void* d_out, int out_size) {
    const float* query  = (const float*)d_in[0];
    const float* kcache = (const float*)d_in[1];
    const float* vcache = (const float*)d_in[2];
    const int*   slots  = (const int*)d_in[3];
    const int*   poss   = (const int*)d_in[4];

    rope_table_kernel<<<(SS * 32 + 255) / 256, 256>>>();
    paged_attn_main<<<BB * KVHH * SPLITS, TPB>>>(query, kcache, vcache, slots, poss);
    combine_kernel<<<(BB * HH * DD + 255) / 256, 256>>>((float*)d_out);
}

// round 9
// speedup vs baseline: 1.3122x; 1.3122x over previous
#include <cuda_runtime.h>
#include <cstdint>

#define BB      32
#define HH      32
#define KVHH    8
#define DD      128
#define SS      2048
#define REP     4          // HH/KVHH
#define SPLITS  8
#define CHUNK   (SS/SPLITS)        // 256
#define TPB     256
#define NWARPS  8
#define TPW     (CHUNK/NWARPS)     // 32 tokens per warp == warp size
#define SCALE_F 0.08838834764831845f   // 1/sqrt(128)
#define ESHIFT  8.0f                   // uniform exp-arg shift; cancels in num/den

// ---------------- device scratch (no allocs allowed) ----------------
// tab4[pos][lane] = {cos(2l), cos(2l+1), sin(2l), sin(2l+1)}  (1 MB)
__device__ float4 g_tab4[SS * 32];
__device__ float g_pacc[BB * KVHH * SPLITS * REP * DD]; // 4 MB split partials (unnormalized)
__device__ float g_pl[BB * KVHH * SPLITS * REP];

// ---------------- rope table (fast MUFU trig with fp32 range reduction) ----------------
__global__ void rope_table_kernel() {
    int idx = blockIdx.x * blockDim.x + threadIdx.x;    // SS*32
    if (idx >= SS * 32) return;
    int pos = idx >> 5, l = idx & 31;
    float inv0 = exp2f(-(float)(2 * l)     * (13.287712379549449f / 64.0f));
    float inv1 = exp2f(-(float)(2 * l + 1) * (13.287712379549449f / 64.0f));
    float a0 = (float)pos * inv0, a1 = (float)pos * inv1;
    float k0 = rintf(a0 * 0.15915494309189535f);
    float k1 = rintf(a1 * 0.15915494309189535f);
    float r0 = fmaf(k0, -6.283185307179586f, a0);
    float r1 = fmaf(k1, -6.283185307179586f, a1);
    float c0, s0, c1, s1;
    __sincosf(r0, &s0, &c0);
    __sincosf(r1, &s1, &c1);
    g_tab4[idx] = make_float4(c0, c1, s0, s1);
}

// ---------------- main split attention kernel (single pass, no max) ----------------
__global__ void __launch_bounds__(TPB, 3)
paged_attn_main(const float* __restrict__ query,
                const float* __restrict__ k_cache,
                const float* __restrict__ v_cache,
                const int*   __restrict__ slot_mapping,
                const int*   __restrict__ positions)
{
    const int cta   = blockIdx.x;
    const int split = cta & (SPLITS - 1);
    const int kvh   = (cta >> 3) & (KVHH - 1);
    const int b     = cta >> 6;
    const int tid   = threadIdx.x;
    const int w     = tid >> 5;
    const int lane  = tid & 31;

    __shared__ __align__(16) float s_acc[REP][NWARPS][DD];   // 16 KB
    __shared__ float s_l[NWARPS][REP];

    const int sbase = split * CHUNK + w * TPW;
    const int* smap = slot_mapping + b * SS + sbase;
    const int* pmap = positions + b * SS + sbase;

    // ---- whole-chunk metadata in registers: lane l holds token l's slot/pos ----
    const int sl_all = __ldg(smap + lane);
    const int ps_all = __ldg(pmap + lane);

    // ---- roped + pre-scaled Q; lane owns dims {2l, 2l+1, 2l+64, 2l+65} ----
    const int posQ = positions[b * SS + (SS - 1)];
    const float4 tq = g_tab4[posQ * 32 + lane];
    float4 qr[REP];
#pragma unroll
    for (int r = 0; r < REP; r++) {
        int h = kvh * REP + r;
        const float* qp = query + ((size_t)b * HH + h) * DD;
        float2 qlo = *(const float2*)(qp + 2 * lane);
        float2 qhi = *(const float2*)(qp + 64 + 2 * lane);
        float4 v;
        v.x = fmaf(-qhi.x, tq.z, qlo.x * tq.x) * SCALE_F;
        v.y = fmaf(-qhi.y, tq.w, qlo.y * tq.y) * SCALE_F;
        v.z = fmaf( qlo.x, tq.z, qhi.x * tq.x) * SCALE_F;
        v.w = fmaf( qlo.y, tq.w, qhi.y * tq.y) * SCALE_F;
        qr[r] = v;
    }

    const float* kbase = k_cache + kvh * DD + 2 * lane;
    const float* vbase = v_cache + kvh * DD + 4 * lane;

    float lown = 0.f;   // per-lane-group l (group g == head g)
    float4 acc0 = make_float4(0.f,0.f,0.f,0.f), acc1 = acc0, acc2 = acc0, acc3 = acc0;

#pragma unroll 1
    for (int t0 = 0; t0 < TPW; t0 += 4) {
        int sl[4], ps[4];
#pragma unroll
        for (int u = 0; u < 4; u++) {
            sl[u] = __shfl_sync(0xffffffffu, sl_all, t0 + u);
            ps[u] = __shfl_sync(0xffffffffu, ps_all, t0 + u);
        }
        float2 klo[4], khi[4];
        float4 vv[4], tb[4];
#pragma unroll
        for (int u = 0; u < 4; u++) {
            klo[u] = make_float2(0.f, 0.f);
            khi[u] = make_float2(0.f, 0.f);
            vv[u]  = make_float4(0.f, 0.f, 0.f, 0.f);
            if (sl[u] >= 0) {
                const float* kp = kbase + (size_t)sl[u] * (KVHH * DD);
                klo[u] = __ldcs((const float2*)kp);
                khi[u] = __ldcs((const float2*)(kp + 64));
                vv[u]  = __ldcs((const float4*)(vbase + (size_t)sl[u] * (KVHH * DD)));
            }
            tb[u] = g_tab4[ps[u] * 32 + lane];
        }
#pragma unroll
        for (int u = 0; u < 4; u++) {
            // rope K in-lane
            float kr0 = fmaf(-khi[u].x, tb[u].z, klo[u].x * tb[u].x);
            float kr1 = fmaf(-khi[u].y, tb[u].w, klo[u].y * tb[u].y);
            float kr2 = fmaf( klo[u].x, tb[u].z, khi[u].x * tb[u].x);
            float kr3 = fmaf( klo[u].y, tb[u].w, khi[u].y * tb[u].y);
            // per-head partial dots
            float v0 = fmaf(kr3, qr[0].w, fmaf(kr2, qr[0].z, fmaf(kr1, qr[0].y, kr0 * qr[0].x)));
            float v1 = fmaf(kr3, qr[1].w, fmaf(kr2, qr[1].z, fmaf(kr1, qr[1].y, kr0 * qr[1].x)));
            float v2 = fmaf(kr3, qr[2].w, fmaf(kr2, qr[2].z, fmaf(kr1, qr[2].y, kr0 * qr[2].x)));
            float v3 = fmaf(kr3, qr[3].w, fmaf(kr2, qr[3].z, fmaf(kr1, qr[3].y, kr0 * qr[3].x)));
            // width-folding reduce: 9 shuffles; 8-lane group g ends with head g's full score
            float r0 = __shfl_xor_sync(0xffffffffu, v0, 16);
            float r1 = __shfl_xor_sync(0xffffffffu, v1, 16);
            float r2 = __shfl_xor_sync(0xffffffffu, v2, 16);
            float r3 = __shfl_xor_sync(0xffffffffu, v3, 16);
            float t0a = v0 + r0, t1a = v1 + r1, t2a = v2 + r2, t3a = v3 + r3;
            float a0 = (lane & 16) ? t2a : t0a;
            float a1 = (lane & 16) ? t3a : t1a;
            float u0 = a0 + __shfl_xor_sync(0xffffffffu, a0, 8);
            float u1 = a1 + __shfl_xor_sync(0xffffffffu, a1, 8);
            float bsum = (lane & 8) ? u1 : u0;
            bsum += __shfl_xor_sync(0xffffffffu, bsum, 4);
            bsum += __shfl_xor_sync(0xffffffffu, bsum, 2);
            bsum += __shfl_xor_sync(0xffffffffu, bsum, 1);
            // one exp per token (per owning group), then broadcast the 4 head p's
            float p = __expf(bsum - ESHIFT);
            lown += p;
            int src = lane & 7;
            float p0 = __shfl_sync(0xffffffffu, p, src);
            float p1 = __shfl_sync(0xffffffffu, p, src | 8);
            float p2 = __shfl_sync(0xffffffffu, p, src | 16);
            float p3 = __shfl_sync(0xffffffffu, p, src | 24);
            float4 v4 = vv[u];
            acc0.x = fmaf(p0, v4.x, acc0.x); acc0.y = fmaf(p0, v4.y, acc0.y);
            acc0.z = fmaf(p0, v4.z, acc0.z); acc0.w = fmaf(p0, v4.w, acc0.w);
            acc1.x = fmaf(p1, v4.x, acc1.x); acc1.y = fmaf(p1, v4.y, acc1.y);
            acc1.z = fmaf(p1, v4.z, acc1.z); acc1.w = fmaf(p1, v4.w, acc1.w);
            acc2.x = fmaf(p2, v4.x, acc2.x); acc2.y = fmaf(p2, v4.y, acc2.y);
            acc2.z = fmaf(p2, v4.z, acc2.z); acc2.w = fmaf(p2, v4.w, acc2.w);
            acc3.x = fmaf(p3, v4.x, acc3.x); acc3.y = fmaf(p3, v4.y, acc3.y);
            acc3.z = fmaf(p3, v4.z, acc3.z); acc3.w = fmaf(p3, v4.w, acc3.w);
        }
    }

    // ---- per-warp state to smem ----
    if ((lane & 7) == 0) s_l[w][lane >> 3] = lown;
    *(float4*)&s_acc[0][w][lane * 4] = acc0;
    *(float4*)&s_acc[1][w][lane * 4] = acc1;
    *(float4*)&s_acc[2][w][lane * 4] = acc2;
    *(float4*)&s_acc[3][w][lane * 4] = acc3;
    __syncthreads();

    // ---- cross-warp merge (plain sums; no factors needed) ----
    const size_t pidx = (size_t)((b * KVHH + kvh) * SPLITS + split);
    const size_t obase = pidx * (REP * DD);
    for (int idx = tid; idx < REP * DD; idx += TPB) {
        int h = idx >> 7, d = idx & (DD - 1);
        float v = 0.f;
#pragma unroll
        for (int ww = 0; ww < NWARPS; ww++) v += s_acc[h][ww][d];
        g_pacc[obase + idx] = v;
    }
    if (tid < REP) {
        float ls = 0.f;
#pragma unroll
        for (int ww = 0; ww < NWARPS; ww++) ls += s_l[ww][tid];
        g_pl[pidx * REP + tid] = ls;
    }
}

// ---------------- split combine ----------------
__global__ void combine_kernel(float* __restrict__ out) {
    int idx = blockIdx.x * blockDim.x + threadIdx.x;
    if (idx >= BB * HH * DD) return;
    int d = idx & (DD - 1);
    int h = (idx >> 7) & (HH - 1);
    int b = idx >> 12;
    int kvh = h >> 2, r = h & 3;
    int pbase = (b * KVHH + kvh) * SPLITS;

    float num = 0.f, den = 0.f;
#pragma unroll
    for (int s = 0; s < SPLITS; s++) {
        den += g_pl[(pbase + s) * REP + r];
        num += g_pacc[(size_t)(pbase + s) * REP * DD + r * DD + d];
    }
    out[idx] = num / den;
}

// ---------------- launch ----------------
extern "C" void kernel_launch(void* const* d_in, const int* in_sizes, int n_in,
                              void* d_out, int out_size) {
    const float* query  = (const float*)d_in[0];
    const float* kcache = (const float*)d_in[1];
    const float* vcache = (const float*)d_in[2];
    const int*   slots  = (const int*)d_in[3];
    const int*   poss   = (const int*)d_in[4];

    rope_table_kernel<<<(SS * 32 + 255) / 256, 256>>>();
    paged_attn_main<<<BB * KVHH * SPLITS, TPB>>>(query, kcache, vcache, slots, poss);
    combine_kernel<<<(BB * HH * DD + 255) / 256, 256>>>((float*)d_out);
}